// round 10
// baseline (speedup 1.0000x reference)
#include <cuda_runtime.h>

#define BN    8
#define NPIX  (224*224)   // 50176
#define SS    196
#define EE    768
#define NBLK  49          // blocks per image in k_main
#define TPB   128         // threads per block in k_main
#define PXT   8           // pixels per thread (49*128*8 = 50176 exactly)
#define OROWS 4           // rows per k_out block; 1568/4 = 392 blocks

// Final accumulators. Zero-initialized at load; k_out re-zeroes after use so
// every kernel_launch call (and every graph replay) starts from zeros.
__device__ float g_sum[BN*SS];   // sum (e - 1)   -> D = NPIX + g_sum
__device__ float g_p0 [BN*SS];   // sum e*c0
__device__ float g_p1 [BN*SS];
__device__ float g_p2 [BN*SS];

// Fused pass: per-pixel 196-way argmax + exp(score); smem segmented
// accumulation; per-block flush via no-return global RED (98 ops/address).
// LSU is the binding pipe: scalar float4 weights (16B per segment, one
// broadcast LDS.128 amortized over 8 pixels) + 4 spread-ATOMS per pixel.
// Argmax: clear low 8 mantissa bits of the logit, embed the segment index,
// carry it through a plain fmaxf chain (perturbation <= 2^-15 rel; harmless
// at the 1e-3 threshold -- measured 2e-5 end-to-end).
__global__ __launch_bounds__(TPB) void k_main(
        const float* __restrict__ img,
        const float* __restrict__ Wseg,
        const float* __restrict__ bseg,
        const float* __restrict__ wq){
    __shared__ float4 sW[SS];
    __shared__ float sSum[SS], sP0[SS], sP1[SS], sP2[SS];
    int t = threadIdx.x;
    for (int i = t; i < SS; i += TPB){
        sW[i] = make_float4(Wseg[3*i], Wseg[3*i+1], Wseg[3*i+2], bseg[i]);
        sSum[i]=0.f; sP0[i]=0.f; sP1[i]=0.f; sP2[i]=0.f;
    }
    __syncthreads();

    int b = blockIdx.y;
    const float* im = img + (size_t)b*3*NPIX;
    int n = (blockIdx.x*TPB + t)*PXT;          // 8 consecutive pixels

    float c0[PXT], c1[PXT], c2[PXT];
    {
        float4 u0 = *(const float4*)(im + n);
        float4 u1 = *(const float4*)(im + n + 4);
        float4 v0 = *(const float4*)(im + NPIX + n);
        float4 v1 = *(const float4*)(im + NPIX + n + 4);
        float4 w0 = *(const float4*)(im + 2*NPIX + n);
        float4 w1 = *(const float4*)(im + 2*NPIX + n + 4);
        c0[0]=u0.x; c0[1]=u0.y; c0[2]=u0.z; c0[3]=u0.w;
        c0[4]=u1.x; c0[5]=u1.y; c0[6]=u1.z; c0[7]=u1.w;
        c1[0]=v0.x; c1[1]=v0.y; c1[2]=v0.z; c1[3]=v0.w;
        c1[4]=v1.x; c1[5]=v1.y; c1[6]=v1.z; c1[7]=v1.w;
        c2[0]=w0.x; c2[1]=w0.y; c2[2]=w0.z; c2[3]=w0.w;
        c2[4]=w1.x; c2[5]=w1.y; c2[6]=w1.z; c2[7]=w1.w;
    }

    float best[PXT];
    #pragma unroll
    for (int p = 0; p < PXT; p++) best[p] = -3.4e38f;

    #pragma unroll 4
    for (int s = 0; s < SS; s++){
        float4 w = sW[s];          // one broadcast LDS.128 per 8 pixels
        #pragma unroll
        for (int p = 0; p < PXT; p++){
            float l = fmaf(c0[p], w.x, fmaf(c1[p], w.y, fmaf(c2[p], w.z, w.w)));
            unsigned u = (__float_as_uint(l) & 0xFFFFFF00u) | (unsigned)s;
            best[p] = fmaxf(best[p], __uint_as_float(u));
        }
    }

    float q0 = wq[0], q1 = wq[1], q2 = wq[2];
    #pragma unroll
    for (int p = 0; p < PXT; p++){
        int s = __float_as_uint(best[p]) & 0xFFu;
        float e = __expf(fmaf(c0[p], q0, fmaf(c1[p], q1, c2[p]*q2)));
        atomicAdd(&sSum[s], e - 1.0f);
        atomicAdd(&sP0[s], e*c0[p]);
        atomicAdd(&sP1[s], e*c1[p]);
        atomicAdd(&sP2[s], e*c2[p]);
    }
    __syncthreads();

    // flush: no-return global REDs; only 49 ops per address -> low contention
    for (int i = t; i < SS; i += TPB){
        int bs = b*SS + i;
        atomicAdd(&g_sum[bs], sSum[i]);
        atomicAdd(&g_p0[bs],  sP0[i]);
        atomicAdd(&g_p1[bs],  sP1[i]);
        atomicAdd(&g_p2[bs],  sP2[i]);
    }
}

// Project: 392 blocks x 128 threads, 4 rows each; Wout held in registers
// (6 e-values per thread), stores coalesced. Resets accumulators after use.
__global__ __launch_bounds__(128) void k_out(
        const float* __restrict__ Wout,
        const float* __restrict__ bout,
        float* __restrict__ out){
    __shared__ float4 srow[OROWS];          // (p0,p1,p2,biasScale)
    int t = threadIdx.x;

    float w0[6], w1[6], w2[6], bb[6];
    #pragma unroll
    for (int k = 0; k < 6; k++){
        int e = t + k*128;
        w0[k] = Wout[3*e]; w1[k] = Wout[3*e+1]; w2[k] = Wout[3*e+2];
        bb[k] = bout[e];
    }

    if (t < OROWS){
        int bs = blockIdx.x*OROWS + t;
        float vs = g_sum[bs];
        float v0 = g_p0[bs], v1 = g_p1[bs], v2 = g_p2[bs];
        float4 rv = make_float4(0.f, 0.f, 0.f, 0.f);
        // present <=> any accumulator touched (exact-0 for a present segment
        // is measure-zero: sums of hundreds of random nonzero terms)
        if (vs != 0.f || v0 != 0.f || v1 != 0.f || v2 != 0.f){
            float D   = (float)NPIX + vs;   // = sum(e) over seg + (NPIX-cnt)
            float inv = 1.0f / D;
            rv = make_float4(v0*inv, v1*inv, v2*inv, 1.0f);
        }
        srow[t] = rv;
        g_sum[bs] = 0.f; g_p0[bs] = 0.f; g_p1[bs] = 0.f; g_p2[bs] = 0.f;
    }
    __syncthreads();

    #pragma unroll
    for (int r = 0; r < OROWS; r++){
        float4 p = srow[r];
        float* o = out + (size_t)(blockIdx.x*OROWS + r)*EE;
        #pragma unroll
        for (int k = 0; k < 6; k++){
            // invalid row => p=(0,0,0,0) -> exact 0 (bias suppressed)
            o[t + k*128] = fmaf(p.x, w0[k], fmaf(p.y, w1[k], fmaf(p.z, w2[k], p.w*bb[k])));
        }
    }
}

extern "C" void kernel_launch(void* const* d_in, const int* in_sizes, int n_in,
                              void* d_out, int out_size) {
    const float* img  = (const float*)d_in[0];   // [8,3,224,224]
    const float* Wseg = (const float*)d_in[1];   // [196,3]
    const float* bseg = (const float*)d_in[2];   // [196]
    const float* wq   = (const float*)d_in[3];   // [3]
    const float* Wout = (const float*)d_in[4];   // [768,3]
    const float* bout = (const float*)d_in[5];   // [768]
    float* out = (float*)d_out;                  // [8,196,768]

    dim3 g(NBLK, BN);                            // 392 blocks
    k_main<<<g, TPB>>>(img, Wseg, bseg, wq);
    k_out<<<(BN*SS)/OROWS, 128>>>(Wout, bout, out);   // 392 blocks
}

// round 11
// speedup vs baseline: 1.0791x; 1.0791x over previous
#include <cuda_runtime.h>

typedef unsigned long long ull;

#define BN    8
#define NPIX  (224*224)   // 50176
#define SS    196
#define EE    768
#define NBLK  49          // blocks per image in k_main
#define TPB   256         // threads per block in k_main
#define PXT   4           // pixels per thread (49*256*4 = 50176 exactly)
#define OROWS 8           // rows per k_out block; 1568/8 = 196 blocks

// Final accumulators. Zero-initialized at load; k_out re-zeroes after use so
// every kernel_launch call (and every graph replay) starts from zeros.
__device__ float g_sum[BN*SS];   // sum (e - 1)   -> D = NPIX + g_sum
__device__ float g_p0 [BN*SS];   // sum e*c0
__device__ float g_p1 [BN*SS];
__device__ float g_p2 [BN*SS];

__device__ __forceinline__ ull ffma2(ull a, ull b, ull c){
    ull d;
    asm("fma.rn.f32x2 %0, %1, %2, %3;" : "=l"(d) : "l"(a), "l"(b), "l"(c));
    return d;
}

// Fused pass: per-pixel 196-way argmax + exp(score); smem segmented
// accumulation; per-block flush via no-return global RED.
// Pipe balancing: packed f32x2 FMA halves fma-pipe load vs scalar; the
// packed weight layout (32B/segment) is read as 2 LDS.128 per segment but
// amortized over 4 pixels -> LDS/pixel is half of the R9 variant.
// Argmax: clear low 8 mantissa bits of each logit, embed the segment index,
// carry it through a plain fmaxf chain (perturbation <= 2^-15 rel; measured
// 2e-5 end-to-end vs the 1e-3 threshold).
__global__ __launch_bounds__(TPB) void k_main(
        const float* __restrict__ img,
        const float* __restrict__ Wseg,
        const float* __restrict__ bseg,
        const float* __restrict__ wq){
    __shared__ __align__(16) float sWp[SS*8];  // per s: wx,wx,wy,wy,wz,wz,wb,wb
    __shared__ float sSum[SS], sP0[SS], sP1[SS], sP2[SS];
    int t = threadIdx.x;
    if (t < SS){
        float wx = Wseg[3*t], wy = Wseg[3*t+1], wz = Wseg[3*t+2], wb = bseg[t];
        float* d = &sWp[t*8];
        d[0]=wx; d[1]=wx; d[2]=wy; d[3]=wy; d[4]=wz; d[5]=wz; d[6]=wb; d[7]=wb;
        sSum[t]=0.f; sP0[t]=0.f; sP1[t]=0.f; sP2[t]=0.f;
    }
    __syncthreads();

    int b = blockIdx.y;
    const float* im = img + (size_t)b*3*NPIX;
    int n = (blockIdx.x*TPB + t)*PXT;          // 4 consecutive pixels

    // U.x=(c0[0],c0[1]) U.y=(c0[2],c0[3]); same for V (ch1), W (ch2)
    ulonglong2 U = *(const ulonglong2*)(im + n);
    ulonglong2 V = *(const ulonglong2*)(im + NPIX + n);
    ulonglong2 Wc = *(const ulonglong2*)(im + 2*NPIX + n);

    float best[PXT];
    #pragma unroll
    for (int p = 0; p < PXT; p++) best[p] = -3.4e38f;

    #pragma unroll 4
    for (int s = 0; s < SS; s++){
        ulonglong2 qa = *(const ulonglong2*)&sWp[s*8];     // (wx,wx),(wy,wy)
        ulonglong2 qb = *(const ulonglong2*)&sWp[s*8 + 4]; // (wz,wz),(wb,wb)
        ull l01 = ffma2(U.x, qa.x, qb.y);
        ull l23 = ffma2(U.y, qa.x, qb.y);
        l01 = ffma2(V.x, qa.y, l01);
        l23 = ffma2(V.y, qa.y, l23);
        l01 = ffma2(Wc.x, qb.x, l01);
        l23 = ffma2(Wc.y, qb.x, l23);
        unsigned u0 = ((unsigned)l01        & 0xFFFFFF00u) | (unsigned)s;
        unsigned u1 = ((unsigned)(l01>>32)  & 0xFFFFFF00u) | (unsigned)s;
        unsigned u2 = ((unsigned)l23        & 0xFFFFFF00u) | (unsigned)s;
        unsigned u3 = ((unsigned)(l23>>32)  & 0xFFFFFF00u) | (unsigned)s;
        best[0] = fmaxf(best[0], __uint_as_float(u0));
        best[1] = fmaxf(best[1], __uint_as_float(u1));
        best[2] = fmaxf(best[2], __uint_as_float(u2));
        best[3] = fmaxf(best[3], __uint_as_float(u3));
    }

    float c0[PXT] = { __uint_as_float((unsigned)U.x), __uint_as_float((unsigned)(U.x>>32)),
                      __uint_as_float((unsigned)U.y), __uint_as_float((unsigned)(U.y>>32)) };
    float c1[PXT] = { __uint_as_float((unsigned)V.x), __uint_as_float((unsigned)(V.x>>32)),
                      __uint_as_float((unsigned)V.y), __uint_as_float((unsigned)(V.y>>32)) };
    float c2[PXT] = { __uint_as_float((unsigned)Wc.x), __uint_as_float((unsigned)(Wc.x>>32)),
                      __uint_as_float((unsigned)Wc.y), __uint_as_float((unsigned)(Wc.y>>32)) };

    float q0 = wq[0], q1 = wq[1], q2 = wq[2];
    #pragma unroll
    for (int p = 0; p < PXT; p++){
        int s = __float_as_uint(best[p]) & 0xFFu;
        float e = __expf(fmaf(c0[p], q0, fmaf(c1[p], q1, c2[p]*q2)));
        atomicAdd(&sSum[s], e - 1.0f);
        atomicAdd(&sP0[s], e*c0[p]);
        atomicAdd(&sP1[s], e*c1[p]);
        atomicAdd(&sP2[s], e*c2[p]);
    }
    __syncthreads();

    // flush: no-return global REDs; only 49 ops per address -> low contention
    if (t < SS){
        int bs = b*SS + t;
        atomicAdd(&g_sum[bs], sSum[t]);
        atomicAdd(&g_p0[bs],  sP0[t]);
        atomicAdd(&g_p1[bs],  sP1[t]);
        atomicAdd(&g_p2[bs],  sP2[t]);
    }
}

// Project: 196 blocks x 256 threads, 8 rows each; Wout held in registers
// (3 e-values per thread), stores coalesced. Resets accumulators after use.
__global__ __launch_bounds__(256) void k_out(
        const float* __restrict__ Wout,
        const float* __restrict__ bout,
        float* __restrict__ out){
    __shared__ float4 srow[OROWS];          // (p0,p1,p2,biasScale)
    int t = threadIdx.x;

    float w0[3], w1[3], w2[3], bb[3];
    #pragma unroll
    for (int k = 0; k < 3; k++){
        int e = t + k*256;
        w0[k] = Wout[3*e]; w1[k] = Wout[3*e+1]; w2[k] = Wout[3*e+2];
        bb[k] = bout[e];
    }

    if (t < OROWS){
        int bs = blockIdx.x*OROWS + t;
        float vs = g_sum[bs];
        float v0 = g_p0[bs], v1 = g_p1[bs], v2 = g_p2[bs];
        float4 rv = make_float4(0.f, 0.f, 0.f, 0.f);
        // present <=> any accumulator touched (exact-0 for a present segment
        // is measure-zero: sums of hundreds of random nonzero terms)
        if (vs != 0.f || v0 != 0.f || v1 != 0.f || v2 != 0.f){
            float D   = (float)NPIX + vs;   // = sum(e) over seg + (NPIX-cnt)
            float inv = 1.0f / D;
            rv = make_float4(v0*inv, v1*inv, v2*inv, 1.0f);
        }
        srow[t] = rv;
        g_sum[bs] = 0.f; g_p0[bs] = 0.f; g_p1[bs] = 0.f; g_p2[bs] = 0.f;
    }
    __syncthreads();

    #pragma unroll
    for (int r = 0; r < OROWS; r++){
        float4 p = srow[r];
        float* o = out + (size_t)(blockIdx.x*OROWS + r)*EE;
        #pragma unroll
        for (int k = 0; k < 3; k++){
            // invalid row => p=(0,0,0,0) -> exact 0 (bias suppressed)
            o[t + k*256] = fmaf(p.x, w0[k], fmaf(p.y, w1[k], fmaf(p.z, w2[k], p.w*bb[k])));
        }
    }
}

extern "C" void kernel_launch(void* const* d_in, const int* in_sizes, int n_in,
                              void* d_out, int out_size) {
    const float* img  = (const float*)d_in[0];   // [8,3,224,224]
    const float* Wseg = (const float*)d_in[1];   // [196,3]
    const float* bseg = (const float*)d_in[2];   // [196]
    const float* wq   = (const float*)d_in[3];   // [3]
    const float* Wout = (const float*)d_in[4];   // [768,3]
    const float* bout = (const float*)d_in[5];   // [768]
    float* out = (float*)d_out;                  // [8,196,768]

    dim3 g(NBLK, BN);                            // 392 blocks
    k_main<<<g, TPB>>>(img, Wseg, bseg, wq);
    k_out<<<(BN*SS)/OROWS, 256>>>(Wout, bout, out);   // 196 blocks
}

// round 13
// speedup vs baseline: 1.1265x; 1.0439x over previous
#include <cuda_runtime.h>

#define BN    8
#define NPIX  (224*224)   // 50176
#define SS    196
#define EE    768
#define NBLK  49          // blocks per image in k_main
#define TPB   256         // threads per block in k_main
#define PXT   4           // pixels per thread (49*256*4 = 50176 exactly)
#define OROWS 8           // rows per k_out block; 1568/8 = 196 blocks

// Final accumulators. Zero-initialized at load; k_out re-zeroes after use so
// every kernel_launch call (and every graph replay) starts from zeros.
__device__ float g_sum[BN*SS];   // sum (e - 1)   -> D = NPIX + g_sum
__device__ float g_p0 [BN*SS];   // sum e*c0
__device__ float g_p1 [BN*SS];
__device__ float g_p2 [BN*SS];

// Fused pass: per-pixel 196-way argmax + exp(score), with warp-level
// RUN-segmented scan aggregation before the shared atomics (same-address
// ATOMS serialization was the dominant cost in all per-pixel-atomic
// variants). R12's bug: label equality is NOT a valid segment predicate when
// a label re-appears in a non-adjacent run (A A B A). Fix: explicit run
// heads via ballot; a lane only accumulates lanes at/after its run head.
__global__ __launch_bounds__(TPB) void k_main(
        const float* __restrict__ img,
        const float* __restrict__ Wseg,
        const float* __restrict__ bseg,
        const float* __restrict__ wq){
    __shared__ float4 sW[SS];
    __shared__ float sSum[SS], sP0[SS], sP1[SS], sP2[SS];
    int t = threadIdx.x, lane = t & 31;
    if (t < SS){
        sW[t] = make_float4(Wseg[3*t], Wseg[3*t+1], Wseg[3*t+2], bseg[t]);
        sSum[t]=0.f; sP0[t]=0.f; sP1[t]=0.f; sP2[t]=0.f;
    }
    __syncthreads();

    int b = blockIdx.y;
    const float* im = img + (size_t)b*3*NPIX;
    int n = (blockIdx.x*TPB + t)*PXT;          // 4 consecutive pixels

    float c0[PXT], c1[PXT], c2[PXT];
    {
        float4 u = *(const float4*)(im + n);
        float4 v = *(const float4*)(im + NPIX + n);
        float4 w = *(const float4*)(im + 2*NPIX + n);
        c0[0]=u.x; c0[1]=u.y; c0[2]=u.z; c0[3]=u.w;
        c1[0]=v.x; c1[1]=v.y; c1[2]=v.z; c1[3]=v.w;
        c2[0]=w.x; c2[1]=w.y; c2[2]=w.z; c2[3]=w.w;
    }

    // Argmax: clear low 8 mantissa bits of the logit, embed segment index,
    // carry through a plain fmaxf chain (<=2^-15 rel perturbation; measured
    // 2e-5 end-to-end vs the 1e-3 threshold).
    float best[PXT];
    #pragma unroll
    for (int p = 0; p < PXT; p++) best[p] = -3.4e38f;

    #pragma unroll 4
    for (int s = 0; s < SS; s++){
        float4 w = sW[s];          // one broadcast LDS.128 per 4 pixels
        #pragma unroll
        for (int p = 0; p < PXT; p++){
            float l = fmaf(c0[p], w.x, fmaf(c1[p], w.y, fmaf(c2[p], w.z, w.w)));
            unsigned u = (__float_as_uint(l) & 0xFFFFFF00u) | (unsigned)s;
            best[p] = fmaxf(best[p], __uint_as_float(u));
        }
    }

    float q0 = wq[0], q1 = wq[1], q2 = wq[2];
    #pragma unroll
    for (int p = 0; p < PXT; p++){
        int lbl = __float_as_uint(best[p]) & 0xFFu;
        float e = __expf(fmaf(c0[p], q0, fmaf(c1[p], q1, c2[p]*q2)));
        float v0 = e - 1.0f, v1 = e*c0[p], v2 = e*c1[p], v3 = e*c2[p];

        // run heads: lane 0, or label differs from predecessor
        int prev = __shfl_up_sync(0xffffffffu, lbl, 1);
        bool head = (lane == 0) || (prev != lbl);
        unsigned hm = __ballot_sync(0xffffffffu, head);
        // nearest head at or below this lane (hm bit0 always set)
        int seg_start = 31 - __clz(hm & (0xFFFFFFFFu >> (31 - lane)));

        // inclusive scan, clipped at the run head
        #pragma unroll
        for (int off = 1; off < 32; off <<= 1){
            float a0 = __shfl_up_sync(0xffffffffu, v0, off);
            float a1 = __shfl_up_sync(0xffffffffu, v1, off);
            float a2 = __shfl_up_sync(0xffffffffu, v2, off);
            float a3 = __shfl_up_sync(0xffffffffu, v3, off);
            if (lane - off >= seg_start){
                v0 += a0; v1 += a1; v2 += a2; v3 += a3;
            }
        }
        // tail = last lane of its run (successor is a head, or lane 31)
        bool tail = (lane == 31) || ((hm >> (lane + 1)) & 1u);
        if (tail){
            atomicAdd(&sSum[lbl], v0);
            atomicAdd(&sP0[lbl],  v1);
            atomicAdd(&sP1[lbl],  v2);
            atomicAdd(&sP2[lbl],  v3);
        }
    }
    __syncthreads();

    // flush: no-return global REDs; only 49 ops per address -> low contention
    if (t < SS){
        int bs = b*SS + t;
        atomicAdd(&g_sum[bs], sSum[t]);
        atomicAdd(&g_p0[bs],  sP0[t]);
        atomicAdd(&g_p1[bs],  sP1[t]);
        atomicAdd(&g_p2[bs],  sP2[t]);
    }
}

// Project: 196 blocks x 256 threads, 8 rows each; Wout held in registers
// (3 e-values per thread), stores coalesced. Resets accumulators after use.
__global__ __launch_bounds__(256) void k_out(
        const float* __restrict__ Wout,
        const float* __restrict__ bout,
        float* __restrict__ out){
    __shared__ float4 srow[OROWS];          // (p0,p1,p2,biasScale)
    int t = threadIdx.x;

    float w0[3], w1[3], w2[3], bb[3];
    #pragma unroll
    for (int k = 0; k < 3; k++){
        int e = t + k*256;
        w0[k] = Wout[3*e]; w1[k] = Wout[3*e+1]; w2[k] = Wout[3*e+2];
        bb[k] = bout[e];
    }

    if (t < OROWS){
        int bs = blockIdx.x*OROWS + t;
        float vs = g_sum[bs];
        float v0 = g_p0[bs], v1 = g_p1[bs], v2 = g_p2[bs];
        float4 rv = make_float4(0.f, 0.f, 0.f, 0.f);
        // present <=> any accumulator touched (exact-0 for a present segment
        // is measure-zero: sums of hundreds of random nonzero terms)
        if (vs != 0.f || v0 != 0.f || v1 != 0.f || v2 != 0.f){
            float D   = (float)NPIX + vs;   // = sum(e) over seg + (NPIX-cnt)
            float inv = 1.0f / D;
            rv = make_float4(v0*inv, v1*inv, v2*inv, 1.0f);
        }
        srow[t] = rv;
        g_sum[bs] = 0.f; g_p0[bs] = 0.f; g_p1[bs] = 0.f; g_p2[bs] = 0.f;
    }
    __syncthreads();

    #pragma unroll
    for (int r = 0; r < OROWS; r++){
        float4 p = srow[r];
        float* o = out + (size_t)(blockIdx.x*OROWS + r)*EE;
        #pragma unroll
        for (int k = 0; k < 3; k++){
            // invalid row => p=(0,0,0,0) -> exact 0 (bias suppressed)
            o[t + k*256] = fmaf(p.x, w0[k], fmaf(p.y, w1[k], fmaf(p.z, w2[k], p.w*bb[k])));
        }
    }
}

extern "C" void kernel_launch(void* const* d_in, const int* in_sizes, int n_in,
                              void* d_out, int out_size) {
    const float* img  = (const float*)d_in[0];   // [8,3,224,224]
    const float* Wseg = (const float*)d_in[1];   // [196,3]
    const float* bseg = (const float*)d_in[2];   // [196]
    const float* wq   = (const float*)d_in[3];   // [3]
    const float* Wout = (const float*)d_in[4];   // [768,3]
    const float* bout = (const float*)d_in[5];   // [768]
    float* out = (float*)d_out;                  // [8,196,768]

    dim3 g(NBLK, BN);                            // 392 blocks
    k_main<<<g, TPB>>>(img, Wseg, bseg, wq);
    k_out<<<(BN*SS)/OROWS, 256>>>(Wout, bout, out);   // 196 blocks
}